// round 14
// baseline (speedup 1.0000x reference)
#include <cuda_runtime.h>
#include <cuda_bf16.h>

#define IN_DIM 4
#define H_DIM 30
#define N_UNIT 100
#define B_MAX 262144

#define K1_TPB 128
#define K1_RPT 2            // rows per thread (one f32x2 pair)

#define K2_TPB 800          // 25 warps; t%25 = fixed unit-group, t/25 = row lane
#define K2_ROWS 256         // rows per block -> grid 1024

typedef unsigned long long u64;

__device__ float g_td[B_MAX];     // residual demand per batch row (scratch)

// ---- packed f32x2 helpers (Blackwell sm_103a) ----
__device__ __forceinline__ u64 f2_fma(u64 a, u64 b, u64 c) {
    u64 d;
    asm("fma.rn.f32x2 %0, %1, %2, %3;" : "=l"(d) : "l"(a), "l"(b), "l"(c));
    return d;
}
__device__ __forceinline__ u64 f2_pack(float lo, float hi) {
    u64 d;
    asm("mov.b64 %0, {%1, %2};" : "=l"(d) : "f"(lo), "f"(hi));
    return d;
}
__device__ __forceinline__ void f2_unpack(u64 v, float& lo, float& hi) {
    asm("mov.b64 {%0, %1}, %2;" : "=f"(lo), "=f"(hi) : "l"(v));
}
__device__ __forceinline__ u64 f2_relu(u64 v) {
    float lo, hi;
    f2_unpack(v, lo, hi);
    return f2_pack(fmaxf(lo, 0.0f), fmaxf(hi, 0.0f));
}
__device__ __forceinline__ u64 splat_bits(float w) {
    unsigned u = __float_as_uint(w);
    return (u64)u | ((u64)u << 32);
}

// ---------------------------------------------------------------------------
// K1: MLP 4->30->30->1, 2 rows/thread via packed f32x2 FMA.
// Weights splatted to (w,w) u64, stored j-MAJOR in shared so consecutive k
// pairs come back as ONE LDS.128 (ulonglong2) -> LDS count halved.
// sum(Pd) folded into the prologue (warp-0 reduction) - no k0 kernel.
// ---------------------------------------------------------------------------
__global__ __launch_bounds__(K1_TPB) void k1_mlp(
    const float* __restrict__ x,
    const float* __restrict__ Pd,
    const float* __restrict__ wcap,
    const float* __restrict__ W1,
    const float* __restrict__ b1,
    const float* __restrict__ W2,
    const float* __restrict__ b2,
    const float* __restrict__ W3,
    const float* __restrict__ b3,
    int B)
{
    __shared__ __align__(16) u64 sW1t[H_DIM][IN_DIM];   // [j][i], 32B rows
    __shared__ __align__(16) u64 sW2t[H_DIM][H_DIM];    // [j][k], 240B rows (16B aligned)
    __shared__ u64 sB1d[H_DIM];
    __shared__ u64 sB2d[H_DIM];
    __shared__ u64 sW3d[H_DIM];
    __shared__ float sPd[K1_TPB];
    __shared__ float sSum, sWc, sB3;

    const int t = threadIdx.x;
    // transpose+splat weights into shared
    for (int idx = t; idx < IN_DIM * H_DIM; idx += K1_TPB) {
        const int i = idx / H_DIM, j = idx % H_DIM;
        sW1t[j][i] = splat_bits(W1[idx]);
    }
    for (int idx = t; idx < H_DIM * H_DIM; idx += K1_TPB) {
        const int k = idx / H_DIM, j = idx % H_DIM;
        sW2t[j][k] = splat_bits(W2[idx]);
    }
    if (t < H_DIM) {
        sB1d[t] = splat_bits(b1[t]);
        sB2d[t] = splat_bits(b2[t]);
        sW3d[t] = splat_bits(W3[t]);
    }
    sPd[t] = (t < N_UNIT) ? Pd[t] : 0.0f;
    if (t == 0) { sB3 = b3[0]; sWc = wcap[0]; }
    __syncthreads();

    // warp 0: reduce sum(Pd)
    if (t < 32) {
        float s = sPd[t] + sPd[t + 32] + sPd[t + 64] + sPd[t + 96];
        #pragma unroll
        for (int off = 16; off > 0; off >>= 1)
            s += __shfl_down_sync(0xFFFFFFFFu, s, off);
        if (t == 0) sSum = s;
    }
    __syncthreads();

    const int rb = (blockIdx.x * K1_TPB + t) * K1_RPT;
    if (rb >= B) return;

    const float4 v0 = *reinterpret_cast<const float4*>(x + 4ll * rb);
    const float4 v1 = *reinterpret_cast<const float4*>(x + 4ll * rb + 4);

    u64 xP[IN_DIM];
    xP[0] = f2_pack(v0.x, v1.x);
    xP[1] = f2_pack(v0.y, v1.y);
    xP[2] = f2_pack(v0.z, v1.z);
    xP[3] = f2_pack(v0.w, v1.w);

    // layer 1: 2 LDS.128 per neuron
    u64 h1P[H_DIM];
    #pragma unroll
    for (int j = 0; j < H_DIM; ++j) {
        const ulonglong2 w01 = *reinterpret_cast<const ulonglong2*>(&sW1t[j][0]);
        const ulonglong2 w23 = *reinterpret_cast<const ulonglong2*>(&sW1t[j][2]);
        u64 a = sB1d[j];
        a = f2_fma(xP[0], w01.x, a);
        a = f2_fma(xP[1], w01.y, a);
        a = f2_fma(xP[2], w23.x, a);
        a = f2_fma(xP[3], w23.y, a);
        h1P[j] = f2_relu(a);
    }

    // layer 2 + output: 15 LDS.128 per neuron, unroll 2 -> 2 indep FMA chains
    u64 yP = f2_pack(sB3, sB3);
    #pragma unroll 2
    for (int j = 0; j < H_DIM; ++j) {
        u64 a = sB2d[j];
        #pragma unroll
        for (int k = 0; k < H_DIM; k += 2) {
            const ulonglong2 w = *reinterpret_cast<const ulonglong2*>(&sW2t[j][k]);
            a = f2_fma(h1P[k],     w.x, a);
            a = f2_fma(h1P[k + 1], w.y, a);
        }
        yP = f2_fma(f2_relu(a), sW3d[j], yP);
    }

    float y0, y1;
    f2_unpack(yP, y0, y1);
    float2 td;
    td.x = sSum - sWc * y0;
    td.y = sSum - sWc * y1;
    *reinterpret_cast<float2*>(g_td + rb) = td;
}

// ---------------------------------------------------------------------------
// K2: dispatch writer. Rank-cumsum computed per block in the prologue
// (t<100, between two barriers, overlapped by co-resident block's streaming).
// Thread owns fixed unit-group g=t%25 (cum/pmax in regs).
// Per iteration: 1 LDS + clip + 1 STG.128 through an incremented pointer.
// ---------------------------------------------------------------------------
__global__ __launch_bounds__(K2_TPB) void k2_dispatch(
    const float* __restrict__ Cost,
    const float* __restrict__ Pmax,
    float* __restrict__ out,
    int B)
{
    __shared__ float sCost[N_UNIT];
    __shared__ float sPm[N_UNIT];
    __shared__ float sCum[N_UNIT];
    __shared__ float sTd[K2_ROWS];

    const int t = threadIdx.x;
    if (t < N_UNIT) { sCost[t] = Cost[t]; sPm[t] = Pmax[t]; }

    const int rowbase = blockIdx.x * K2_ROWS;
    if (t < K2_ROWS) {
        const int r = rowbase + t;
        sTd[t] = (r < B) ? g_td[r] : 0.0f;
    }
    __syncthreads();

    // exclusive cumulative capacity of strictly-cheaper units (stable rank)
    if (t < N_UNIT) {
        const float c = sCost[t];
        float s = 0.0f;
        #pragma unroll 4
        for (int j = 0; j < N_UNIT; ++j) {
            const float cj = sCost[j];
            if (cj < c || (cj == c && j < t)) s += sPm[j];
        }
        sCum[t] = s;
    }
    __syncthreads();

    const int g  = t % 25;          // unit-group: units [4g, 4g+4)
    const int r0 = t / 25;          // 0..31
    float4 cum4, pm4;
    cum4.x = sCum[4 * g + 0]; cum4.y = sCum[4 * g + 1];
    cum4.z = sCum[4 * g + 2]; cum4.w = sCum[4 * g + 3];
    pm4.x  = sPm[4 * g + 0]; pm4.y = sPm[4 * g + 1];
    pm4.z  = sPm[4 * g + 2]; pm4.w = sPm[4 * g + 3];

    float4* p = reinterpret_cast<float4*>(out) +
                ((long long)(rowbase + r0) * 25 + g);
    int rl = r0;

    #pragma unroll
    for (int k = 0; k < K2_ROWS / 32; ++k) {
        if (rowbase + rl >= B) break;
        const float td = sTd[rl];
        float4 v;
        v.x = fminf(fmaxf(td - cum4.x, 0.0f), pm4.x);
        v.y = fminf(fmaxf(td - cum4.y, 0.0f), pm4.y);
        v.z = fminf(fmaxf(td - cum4.z, 0.0f), pm4.z);
        v.w = fminf(fmaxf(td - cum4.w, 0.0f), pm4.w);
        *p = v;
        rl += 32;
        p  += 32 * 25;              // 32 rows * 25 float4/row
    }
}

extern "C" void kernel_launch(void* const* d_in, const int* in_sizes, int n_in,
                              void* d_out, int out_size) {
    const float* x    = (const float*)d_in[0];
    const float* Cost = (const float*)d_in[1];
    const float* Pmax = (const float*)d_in[2];
    const float* Pd   = (const float*)d_in[3];
    const float* wcap = (const float*)d_in[4];
    const float* W1   = (const float*)d_in[5];
    const float* b1   = (const float*)d_in[6];
    const float* W2   = (const float*)d_in[7];
    const float* b2   = (const float*)d_in[8];
    const float* W3   = (const float*)d_in[9];
    const float* b3   = (const float*)d_in[10];
    float* out = (float*)d_out;

    const int B = in_sizes[0] / IN_DIM;

    const int grid1 = (B + K1_TPB * K1_RPT - 1) / (K1_TPB * K1_RPT);
    k1_mlp<<<grid1, K1_TPB>>>(x, Pd, wcap, W1, b1, W2, b2, W3, b3, B);

    const int grid2 = (B + K2_ROWS - 1) / K2_ROWS;
    k2_dispatch<<<grid2, K2_TPB>>>(Cost, Pmax, out, B);
}